// round 9
// baseline (speedup 1.0000x reference)
#include <cuda_runtime.h>
#include <cuda_fp16.h>
#include <math.h>
#include <stdint.h>

// Problem constants
constexpr int B_ = 64;
constexpr int T_ = 256;
constexpr int D_ = 512;
constexpr int H_ = 1024;
constexpr int G4 = 4 * H_;         // 4096
constexpr int BH = B_ * H_;        // 65536

// ------------------------- device scratch (no allocs) ----------------------
__device__ float  g_xw[(size_t)B_ * T_ * G4];        // (B*T, 4H) fp32
__device__ float  g_c[BH];                           // cell state fp32
__device__ __half g_h16[2 * BH];                     // double-buffered hidden
__device__ __half g_x16[(size_t)B_ * T_ * D_];
__device__ __half g_W1_16[(size_t)D_ * G4];
__device__ __half g_U1_16[(size_t)H_ * G4];
__device__ __half g_W2_16[(size_t)H_ * G4];
__device__ __half g_U2_16[(size_t)H_ * G4];
__device__ __half g_fc1w16[(size_t)H_ * (H_ / 2)];
__device__ __half g_ys1_16[(size_t)B_ * T_ * H_];
__device__ __half g_ys2_16[(size_t)B_ * T_ * H_];
__device__ float  g_z1[(size_t)B_ * T_ * (H_ / 2)];
__device__ float  g_z2[B_ * 36];
__device__ int    g_cnt[T_ * 8];                     // [t][bh][q] arrivals

// ------------------------------ PTX helpers --------------------------------
__device__ __forceinline__ uint32_t smem_u32(const void* p) {
    uint32_t a;
    asm("{ .reg .u64 t; cvta.to.shared.u64 t, %1; cvt.u32.u64 %0, t; }"
        : "=r"(a) : "l"(p));
    return a;
}
__device__ __forceinline__ void cp_async16(uint32_t dst, const void* src) {
    asm volatile("cp.async.cg.shared.global [%0], [%1], 16;" :: "r"(dst), "l"(src));
}
__device__ __forceinline__ void cp_commit() {
    asm volatile("cp.async.commit_group;");
}
template <int N> __device__ __forceinline__ void cp_wait_n() {
    asm volatile("cp.async.wait_group %0;" :: "n"(N));
}
__device__ __forceinline__ void ldmatrix_x4(uint32_t* r, uint32_t addr) {
    asm volatile("ldmatrix.sync.aligned.m8n8.x4.shared.b16 {%0,%1,%2,%3}, [%4];"
                 : "=r"(r[0]), "=r"(r[1]), "=r"(r[2]), "=r"(r[3]) : "r"(addr));
}
__device__ __forceinline__ void ldmatrix_x4t(uint32_t* r, uint32_t addr) {
    asm volatile("ldmatrix.sync.aligned.m8n8.x4.trans.shared.b16 {%0,%1,%2,%3}, [%4];"
                 : "=r"(r[0]), "=r"(r[1]), "=r"(r[2]), "=r"(r[3]) : "r"(addr));
}
__device__ __forceinline__ void ldmatrix_x2t(uint32_t* r, uint32_t addr) {
    asm volatile("ldmatrix.sync.aligned.m8n8.x2.trans.shared.b16 {%0,%1}, [%2];"
                 : "=r"(r[0]), "=r"(r[1]) : "r"(addr));
}
__device__ __forceinline__ void mma16816(float* d, const uint32_t* a, const uint32_t* b) {
    asm volatile(
        "mma.sync.aligned.m16n8k16.row.col.f32.f16.f16.f32 "
        "{%0,%1,%2,%3},{%4,%5,%6,%7},{%8,%9},{%0,%1,%2,%3};"
        : "+f"(d[0]), "+f"(d[1]), "+f"(d[2]), "+f"(d[3])
        : "r"(a[0]), "r"(a[1]), "r"(a[2]), "r"(a[3]), "r"(b[0]), "r"(b[1]));
}
// acquire load (volatile asm — cannot be hoisted or deleted)
__device__ __forceinline__ int ld_acquire_gpu(const int* p) {
    int v;
    asm volatile("ld.acquire.gpu.global.s32 %0, [%1];" : "=r"(v) : "l"(p) : "memory");
    return v;
}
// release reduction
__device__ __forceinline__ void red_release_add(int* p, int v) {
    asm volatile("red.release.gpu.global.add.s32 [%0], %1;" :: "l"(p), "r"(v) : "memory");
}

__device__ __forceinline__ float sigmoidf_(float x) { return 1.f / (1.f + expf(-x)); }

// ---------------------------------------------------------------------------
__global__ void f32_to_f16(const float* __restrict__ in, __half* __restrict__ out, int n)
{
    int i4 = (blockIdx.x * 256 + threadIdx.x) * 4;
    if (i4 < n) {
        float4 v = *reinterpret_cast<const float4*>(in + i4);
        *reinterpret_cast<__half2*>(out + i4)     = __floats2half2_rn(v.x, v.y);
        *reinterpret_cast<__half2*>(out + i4 + 2) = __floats2half2_rn(v.z, v.w);
    }
}

__global__ void init_h16(const float* __restrict__ h0, __half* __restrict__ h16)
{
    int i = blockIdx.x * 256 + threadIdx.x;
    if (i < BH) h16[i] = __float2half_rn(h0[i]);   // seed buffer 0
}

__global__ void reset_cnt(int* cnt)
{
    int i = blockIdx.x * 256 + threadIdx.x;
    if (i < T_ * 8) cnt[i] = 0;
}

// ---------------------------------------------------------------------------
// HGEMM: C_fp32(M,N) = A_fp16(M,K) @ B_fp16(K,N) + bias(N)
// 128x128x32 tile, 256 threads, double-buffered cp.async.
// ---------------------------------------------------------------------------
__global__ void __launch_bounds__(256) hgemm(
    const __half* __restrict__ A, const __half* __restrict__ Bm,
    const float* __restrict__ bias, float* __restrict__ C,
    int M, int N, int K)
{
    __shared__ __half As[2][128 * 40];
    __shared__ __half Bs[2][32 * 136];

    const int tid = threadIdx.x;
    const int w = tid >> 5, lane = tid & 31;
    const int bm = blockIdx.y * 128, bn = blockIdx.x * 128;
    const int wm = (w >> 2) * 64, wn = (w & 3) * 32;
    const uint32_t AsU = smem_u32(As), BsU = smem_u32(Bs);

    float acc[4][4][4];
#pragma unroll
    for (int i = 0; i < 4; i++)
#pragma unroll
        for (int j = 0; j < 4; j++)
#pragma unroll
            for (int e = 0; e < 4; e++) acc[i][j][e] = 0.f;

    const int nk = K / 32;

#define LOAD_TILE(kt, buf)                                                        \
    {                                                                             \
        int k0 = (kt) * 32;                                                       \
        _Pragma("unroll")                                                         \
        for (int e = 0; e < 2; e++) {                                             \
            int idx = tid + e * 256;                                              \
            int r = idx >> 2, ch = idx & 3;                                       \
            cp_async16(AsU + ((buf) * 5120 + r * 40 + ch * 8) * 2,                \
                       A + (size_t)(bm + r) * K + k0 + ch * 8);                   \
        }                                                                         \
        _Pragma("unroll")                                                         \
        for (int e = 0; e < 2; e++) {                                             \
            int idx = tid + e * 256;                                              \
            int r = idx >> 4, ch = idx & 15;                                      \
            cp_async16(BsU + ((buf) * 4352 + r * 136 + ch * 8) * 2,               \
                       Bm + (size_t)(k0 + r) * N + bn + ch * 8);                  \
        }                                                                         \
        cp_commit();                                                              \
    }

    LOAD_TILE(0, 0)
    cp_wait_n<0>();
    __syncthreads();

    for (int kt = 0; kt < nk; kt++) {
        int buf = kt & 1;
        if (kt + 1 < nk) LOAD_TILE(kt + 1, buf ^ 1)

#pragma unroll
        for (int ks = 0; ks < 2; ks++) {
            uint32_t bfr[4][2];
#pragma unroll
            for (int nf = 0; nf < 4; nf++)
                ldmatrix_x2t(bfr[nf],
                    BsU + (buf * 4352 + (ks * 16 + (lane & 15)) * 136 + wn + nf * 8) * 2);
#pragma unroll
            for (int mf = 0; mf < 4; mf++) {
                uint32_t afr[4];
                ldmatrix_x4(afr,
                    AsU + (buf * 5120 + (wm + mf * 16 + (lane & 15)) * 40
                           + ks * 16 + ((lane >> 4) * 8)) * 2);
#pragma unroll
                for (int nf = 0; nf < 4; nf++) mma16816(acc[mf][nf], afr, bfr[nf]);
            }
        }
        if (kt + 1 < nk) cp_wait_n<0>();
        __syncthreads();
    }
#undef LOAD_TILE

    const int g = lane >> 2, t4 = lane & 3;
#pragma unroll
    for (int mf = 0; mf < 4; mf++)
#pragma unroll
        for (int nf = 0; nf < 4; nf++) {
            int row0 = bm + wm + mf * 16 + g;
            int col = bn + wn + nf * 8 + t4 * 2;
            float b0 = bias ? bias[col] : 0.f;
            float b1 = bias ? bias[col + 1] : 0.f;
            C[(size_t)row0 * N + col]           = acc[mf][nf][0] + b0;
            C[(size_t)row0 * N + col + 1]       = acc[mf][nf][1] + b1;
            C[(size_t)(row0 + 8) * N + col]     = acc[mf][nf][2] + b0;
            C[(size_t)(row0 + 8) * N + col + 1] = acc[mf][nf][3] + b1;
        }
}

// ---------------------------------------------------------------------------
// Persistent tensor-core LSTM v4. 128 CTAs = 64 j-groups x 2 batch halves.
//  - h double-buffered: read buf t&1, write buf (t+1)&1.
//  - CHUNKED one-sided sync: counters cnt[t][bh][q], q = j-range/256.
//    Each CTA produces 16 j-cols in exactly one chunk (q = jg>>4) and
//    arrives once (bar.sync + red.release — the bar creates the
//    happens-before edges from all threads' h-stores to the release).
//    Consumers acquire-spin per chunk right before issuing that chunk's
//    staging, overlapping chunk-0 stage/compute with chunk-1..3 stragglers.
//    WAR-safe: a CTA reaches step t only after all same-bh CTAs arrived at
//    t-1, and arrival is after that CTA's own staging reads of step t-1.
// ---------------------------------------------------------------------------
constexpr int U_BYTES   = 1024 * 72 * 2;   // 147456
constexpr int A_BYTES   = 32 * 1032 * 2;   // 66048
constexpr int LSTM_SMEM = U_BYTES + A_BYTES;  // 213504

__global__ void __launch_bounds__(256) lstm_layer_tc4(
    const __half* __restrict__ U16,   // (1024, 4096) fp16
    const float* __restrict__ xw,     // (B*T, 4096) fp32, rows b*T+t
    const float* __restrict__ cseed,  // (B,1024) fp32 initial cell
    float* __restrict__ cout,         // (B,1024) fp32 final cell
    __half* __restrict__ h16,         // [2][B][1024] fp16 (buf0 pre-seeded)
    __half* __restrict__ ys16,        // (B*T, 1024) fp16 out
    int* __restrict__ cnt)            // [T][2][4] arrival counters (zeroed)
{
    extern __shared__ char sm[];
    __half* U_s = (__half*)sm;                 // [1024][72]
    __half* A_s = (__half*)(sm + U_BYTES);     // [32][1032]
    float*  red = (float*)(sm + U_BYTES);      // alias: per-warp [32][10] fp32
    const uint32_t U_u = smem_u32(U_s);
    const uint32_t A_u = smem_u32(A_s);

    const int tid = threadIdx.x;
    const int w = tid >> 5, lane = tid & 31;
    const int jg = blockIdx.x >> 1;            // 0..63
    const int bh = blockIdx.x & 1;             // batch half
    const int j0 = jg * 16;
    const int qself = jg >> 4;                 // this CTA's column chunk

    // ---- preload U slice: U_s[k][w*8 + 2*gate + jj] = U16[k][gate*H + j0 + 2w + jj]
    for (int i = 0; i < 128; i++) {
        int idx = tid + i * 256;
        int k = idx >> 5;
        int gate = (idx >> 3) & 3;
        int ww = idx & 7;
        *reinterpret_cast<__half2*>(U_s + k * 72 + ww * 8 + 2 * gate) =
            *reinterpret_cast<const __half2*>(U16 + (size_t)k * G4 + gate * H_ + j0 + 2 * ww);
    }
    __syncthreads();

    const int bloc = bh * 32 + lane;
    float2 creg = *reinterpret_cast<const float2*>(cseed + (size_t)bloc * H_ + j0 + 2 * w);

    float* redw = red + w * 320;               // [32][10]

    for (int t = 0; t < T_; t++) {
        // prefetch xw for this lane's two cells (independent of h)
        float2 xg[4];
        {
            size_t xbase = ((size_t)bloc * T_ + t) * (size_t)G4 + j0 + 2 * w;
#pragma unroll
            for (int gg = 0; gg < 4; gg++)
                xg[gg] = __ldg(reinterpret_cast<const float2*>(xw + xbase + (size_t)gg * H_));
        }

        const __half* hg = h16 + (size_t)(t & 1) * BH + (size_t)bh * 32 * H_;

        // per-chunk: acquire-spin on that chunk's producers, then issue its staging
#pragma unroll
        for (int q = 0; q < 4; q++) {
            if (t > 0) {
                const int* cp = &cnt[(t - 1) * 8 + bh * 4 + q];
                while ((unsigned)ld_acquire_gpu(cp) < 16u) { }
            }
#pragma unroll
            for (int e = 0; e < 4; e++) {
                int idx = tid + e * 256;
                int r = idx >> 5, ch = idx & 31;
                cp_async16(A_u + (r * 1032 + q * 256 + ch * 8) * 2,
                           hg + (size_t)r * H_ + q * 256 + ch * 8);
            }
            cp_commit();
        }

        float acc0[4], acc1[4];
#pragma unroll
        for (int e = 0; e < 4; e++) { acc0[e] = 0.f; acc1[e] = 0.f; }

#define LSTM_MMA_CHUNK(C, WAITN)                                                   \
        {                                                                          \
            cp_wait_n<WAITN>();                                                    \
            __syncthreads();                                                       \
            _Pragma("unroll")                                                      \
            for (int ks2 = 0; ks2 < 8; ks2++) {                                    \
                int kk = (C) * 256 + ks2 * 32;                                     \
                uint32_t bq[4];                                                    \
                ldmatrix_x4t(bq, U_u + ((kk + lane) * 72 + w * 8) * 2);            \
                uint32_t a0[4], a1[4];                                             \
                ldmatrix_x4(a0, A_u + (((lane & 15)) * 1032                        \
                                       + kk + (lane >> 4) * 8) * 2);               \
                ldmatrix_x4(a1, A_u + ((16 + (lane & 15)) * 1032                   \
                                       + kk + (lane >> 4) * 8) * 2);               \
                mma16816(acc0, a0, bq);                                            \
                mma16816(acc1, a1, bq);                                            \
                uint32_t a2[4], a3[4];                                             \
                ldmatrix_x4(a2, A_u + (((lane & 15)) * 1032                        \
                                       + kk + 16 + (lane >> 4) * 8) * 2);          \
                ldmatrix_x4(a3, A_u + ((16 + (lane & 15)) * 1032                   \
                                       + kk + 16 + (lane >> 4) * 8) * 2);          \
                mma16816(acc0, a2, bq + 2);                                        \
                mma16816(acc1, a3, bq + 2);                                        \
            }                                                                      \
        }
        LSTM_MMA_CHUNK(0, 3)
        LSTM_MMA_CHUNK(1, 2)
        LSTM_MMA_CHUNK(2, 1)
        LSTM_MMA_CHUNK(3, 0)
#undef LSTM_MMA_CHUNK

        __syncthreads();   // all warps done reading A_s; red alias now safe

        // warp-private gate transpose: redw[row][col], col = 2*gate + jj
        {
            const int g_ = lane >> 2, t4 = lane & 3;
            redw[(g_)      * 10 + 2 * t4]     = acc0[0];
            redw[(g_)      * 10 + 2 * t4 + 1] = acc0[1];
            redw[(g_ + 8)  * 10 + 2 * t4]     = acc0[2];
            redw[(g_ + 8)  * 10 + 2 * t4 + 1] = acc0[3];
            redw[(g_ + 16) * 10 + 2 * t4]     = acc1[0];
            redw[(g_ + 16) * 10 + 2 * t4 + 1] = acc1[1];
            redw[(g_ + 24) * 10 + 2 * t4]     = acc1[2];
            redw[(g_ + 24) * 10 + 2 * t4 + 1] = acc1[3];
        }
        __syncwarp();

        // cell update: lane handles row=lane (bloc), both j
        {
            float iva = redw[lane * 10 + 0] + xg[0].x;
            float ivb = redw[lane * 10 + 1] + xg[0].y;
            float fva = redw[lane * 10 + 2] + xg[1].x;
            float fvb = redw[lane * 10 + 3] + xg[1].y;
            float gva = redw[lane * 10 + 4] + xg[2].x;
            float gvb = redw[lane * 10 + 5] + xg[2].y;
            float ova = redw[lane * 10 + 6] + xg[3].x;
            float ovb = redw[lane * 10 + 7] + xg[3].y;

            float cna = sigmoidf_(fva) * creg.x + sigmoidf_(iva) * tanhf(gva);
            float cnb = sigmoidf_(fvb) * creg.y + sigmoidf_(ivb) * tanhf(gvb);
            float hna = sigmoidf_(ova) * tanhf(cna);
            float hnb = sigmoidf_(ovb) * tanhf(cnb);
            creg.x = cna; creg.y = cnb;

            __half2 h2 = __floats2half2_rn(hna, hnb);
            *reinterpret_cast<__half2*>(
                h16 + (size_t)((t + 1) & 1) * BH + (size_t)bloc * H_ + j0 + 2 * w) = h2;
            *reinterpret_cast<__half2*>(
                ys16 + ((size_t)bloc * T_ + t) * (size_t)H_ + j0 + 2 * w) = h2;
        }

        // arrive: bar.sync orders all threads' h-stores before tid0's release
        __syncthreads();
        if (tid == 0) red_release_add(&cnt[t * 8 + bh * 4 + qself], 1);
    }

    // write back final cell state
    *reinterpret_cast<float2*>(cout + (size_t)bloc * H_ + j0 + 2 * w) = creg;
}

// ---------------------------------------------------------------------------
// fc2 split-K: z2(64,36) += z1(64,131072) @ W(131072,36); z2 pre-seeded w/ bias
// ---------------------------------------------------------------------------
constexpr int FC2_SMEM = 256 * 65 * 4 + 256 * 37 * 4;  // 104448

__global__ void __launch_bounds__(256) fc2_split(
    const float* __restrict__ z1, const float* __restrict__ W,
    float* __restrict__ z2)
{
    extern __shared__ float smf[];
    float* As = smf;                 // [256 k][65 m-pad]
    float* Ws = smf + 256 * 65;      // [256 k][37 n-pad]
    const int k0 = blockIdx.x * 256;
    const int tid = threadIdx.x;

    for (int i = 0; i < 16; i++) {
        int idx = tid + i * 256;
        int m = idx >> 6, kc = (idx & 63) * 4;
        float4 v = *reinterpret_cast<const float4*>(z1 + (size_t)m * 131072 + k0 + kc);
        As[(kc + 0) * 65 + m] = v.x;
        As[(kc + 1) * 65 + m] = v.y;
        As[(kc + 2) * 65 + m] = v.z;
        As[(kc + 3) * 65 + m] = v.w;
    }
    for (int i = 0; i < 36; i++) {
        int idx = tid + i * 256;
        int k = idx / 36, n = idx - k * 36;
        Ws[k * 37 + n] = W[(size_t)(k0 + k) * 36 + n];
    }
    __syncthreads();

    const int m = tid & 63, ng = tid >> 6;
    const int n0 = ng * 9;
    float acc[9];
#pragma unroll
    for (int j = 0; j < 9; j++) acc[j] = 0.f;

    for (int k = 0; k < 256; k++) {
        float a = As[k * 65 + m];
#pragma unroll
        for (int j = 0; j < 9; j++) acc[j] = fmaf(a, Ws[k * 37 + n0 + j], acc[j]);
    }
#pragma unroll
    for (int j = 0; j < 9; j++) atomicAdd(&z2[m * 36 + n0 + j], acc[j]);
}

__global__ void z2_init(const float* __restrict__ bias, float* __restrict__ z2)
{
    int i = blockIdx.x * 256 + threadIdx.x;
    if (i < B_ * 36) z2[i] = bias[i % 36];
}

// fc3 (36->6) + fc4 (6->6) + relu
__global__ void fc34_kernel(const float* __restrict__ z2,
                            const float* __restrict__ w3, const float* __restrict__ b3,
                            const float* __restrict__ w4, const float* __restrict__ b4,
                            float* __restrict__ out)
{
    int m = threadIdx.x;
    if (m >= B_) return;
    float t3[6];
#pragma unroll
    for (int n = 0; n < 6; n++) {
        float s = b3[n];
        for (int k = 0; k < 36; k++) s = fmaf(z2[m * 36 + k], w3[k * 6 + n], s);
        t3[n] = s;
    }
#pragma unroll
    for (int n = 0; n < 6; n++) {
        float s = b4[n];
#pragma unroll
        for (int k = 0; k < 6; k++) s = fmaf(t3[k], w4[k * 6 + n], s);
        out[m * 6 + n] = fmaxf(s, 0.f);
    }
}

// ---------------------------------------------------------------------------
extern "C" void kernel_launch(void* const* d_in, const int* in_sizes, int n_in,
                              void* d_out, int out_size)
{
    const float* x     = (const float*)d_in[0];
    const float* h0    = (const float*)d_in[1];
    const float* c0    = (const float*)d_in[2];
    const float* W1    = (const float*)d_in[3];
    const float* U1    = (const float*)d_in[4];
    const float* b1    = (const float*)d_in[5];
    const float* W2    = (const float*)d_in[6];
    const float* U2    = (const float*)d_in[7];
    const float* b2    = (const float*)d_in[8];
    const float* fc1_w = (const float*)d_in[9];
    const float* fc1_b = (const float*)d_in[10];
    const float* fc2_w = (const float*)d_in[11];
    const float* fc2_b = (const float*)d_in[12];
    const float* fc3_w = (const float*)d_in[13];
    const float* fc3_b = (const float*)d_in[14];
    const float* fc4_w = (const float*)d_in[15];
    const float* fc4_b = (const float*)d_in[16];
    float* out = (float*)d_out;

    float *xw, *c, *z1, *z2;
    int* cnt;
    __half *h16, *x16, *W1_16, *U1_16, *W2_16, *U2_16, *fc1w16, *ys1_16, *ys2_16;
    cudaGetSymbolAddress((void**)&xw, g_xw);
    cudaGetSymbolAddress((void**)&c, g_c);
    cudaGetSymbolAddress((void**)&h16, g_h16);
    cudaGetSymbolAddress((void**)&x16, g_x16);
    cudaGetSymbolAddress((void**)&W1_16, g_W1_16);
    cudaGetSymbolAddress((void**)&U1_16, g_U1_16);
    cudaGetSymbolAddress((void**)&W2_16, g_W2_16);
    cudaGetSymbolAddress((void**)&U2_16, g_U2_16);
    cudaGetSymbolAddress((void**)&fc1w16, g_fc1w16);
    cudaGetSymbolAddress((void**)&ys1_16, g_ys1_16);
    cudaGetSymbolAddress((void**)&ys2_16, g_ys2_16);
    cudaGetSymbolAddress((void**)&z1, g_z1);
    cudaGetSymbolAddress((void**)&z2, g_z2);
    cudaGetSymbolAddress((void**)&cnt, g_cnt);

    static bool attr_done = false;
    if (!attr_done) {
        cudaFuncSetAttribute(lstm_layer_tc4,
                             cudaFuncAttributeMaxDynamicSharedMemorySize, LSTM_SMEM);
        cudaFuncSetAttribute(fc2_split,
                             cudaFuncAttributeMaxDynamicSharedMemorySize, FC2_SMEM);
        attr_done = true;
    }

    const int MT = B_ * T_;  // 16384

    auto conv = [](const float* src, __half* dst, int n) {
        f32_to_f16<<<(n / 4 + 255) / 256, 256>>>(src, dst, n);
    };
    conv(x, x16, MT * D_);
    conv(W1, W1_16, D_ * G4);
    conv(U1, U1_16, H_ * G4);
    conv(W2, W2_16, H_ * G4);
    conv(U2, U2_16, H_ * G4);
    conv(fc1_w, fc1w16, H_ * (H_ / 2));
    init_h16<<<BH / 256, 256>>>(h0, h16);

    // xw = x @ W1 + b1
    hgemm<<<dim3(G4 / 128, MT / 128), 256>>>(x16, W1_16, b1, xw, MT, G4, D_);

    // LSTM layer 1 (c seeded from c0, final c -> g_c)
    reset_cnt<<<8, 256>>>(cnt);
    lstm_layer_tc4<<<128, 256, LSTM_SMEM>>>(U1_16, xw, c0, c, h16, ys1_16, cnt);

    // xw = ys1 @ W2 + b2
    hgemm<<<dim3(G4 / 128, MT / 128), 256>>>(ys1_16, W2_16, b2, xw, MT, G4, H_);

    // LSTM layer 2 (h16 buf0 / c carry over — matches reference seeding)
    reset_cnt<<<8, 256>>>(cnt);
    lstm_layer_tc4<<<128, 256, LSTM_SMEM>>>(U2_16, xw, c, c, h16, ys2_16, cnt);

    // z1 = ys2 @ fc1_w + fc1_b
    hgemm<<<dim3((H_ / 2) / 128, MT / 128), 256>>>(ys2_16, fc1w16, fc1_b, z1,
                                                   MT, H_ / 2, H_);

    // fc2: z2 = bias, then split-K accumulate
    z2_init<<<(B_ * 36 + 255) / 256, 256>>>(fc2_b, z2);
    fc2_split<<<512, 256, FC2_SMEM>>>(z1, fc2_w, z2);

    // fc3 + fc4 + relu -> out (64, 6)
    fc34_kernel<<<1, 64>>>(z2, fc3_w, fc3_b, fc4_w, fc4_b, out);
}

// round 10
// speedup vs baseline: 1.2391x; 1.2391x over previous
#include <cuda_runtime.h>
#include <cuda_fp16.h>
#include <math.h>
#include <stdint.h>

// Problem constants
constexpr int B_ = 64;
constexpr int T_ = 256;
constexpr int D_ = 512;
constexpr int H_ = 1024;
constexpr int G4 = 4 * H_;         // 4096
constexpr int BH = B_ * H_;        // 65536

// ------------------------- device scratch (no allocs) ----------------------
__device__ float  g_xw[(size_t)B_ * T_ * G4];        // (B*T, 4H) fp32
__device__ float  g_c[BH];                           // cell state fp32
__device__ __half g_h16[2 * BH];                     // double-buffered hidden
__device__ __half g_x16[(size_t)B_ * T_ * D_];
__device__ __half g_W1_16[(size_t)D_ * G4];
__device__ __half g_U1_16[(size_t)H_ * G4];
__device__ __half g_W2_16[(size_t)H_ * G4];
__device__ __half g_U2_16[(size_t)H_ * G4];
__device__ __half g_fc1w16[(size_t)H_ * (H_ / 2)];
__device__ __half g_ys1_16[(size_t)B_ * T_ * H_];
__device__ __half g_ys2_16[(size_t)B_ * T_ * H_];
__device__ float  g_z1[(size_t)B_ * T_ * (H_ / 2)];
__device__ float  g_z2[B_ * 36];
__device__ int    g_cnt[T_ * 2];                     // [t][bh] arrivals

// ------------------------------ PTX helpers --------------------------------
__device__ __forceinline__ uint32_t smem_u32(const void* p) {
    uint32_t a;
    asm("{ .reg .u64 t; cvta.to.shared.u64 t, %1; cvt.u32.u64 %0, t; }"
        : "=r"(a) : "l"(p));
    return a;
}
__device__ __forceinline__ void cp_async16(uint32_t dst, const void* src) {
    asm volatile("cp.async.cg.shared.global [%0], [%1], 16;" :: "r"(dst), "l"(src));
}
__device__ __forceinline__ void cp_commit() {
    asm volatile("cp.async.commit_group;");
}
template <int N> __device__ __forceinline__ void cp_wait_n() {
    asm volatile("cp.async.wait_group %0;" :: "n"(N));
}
__device__ __forceinline__ void ldmatrix_x4(uint32_t* r, uint32_t addr) {
    asm volatile("ldmatrix.sync.aligned.m8n8.x4.shared.b16 {%0,%1,%2,%3}, [%4];"
                 : "=r"(r[0]), "=r"(r[1]), "=r"(r[2]), "=r"(r[3]) : "r"(addr));
}
__device__ __forceinline__ void ldmatrix_x4t(uint32_t* r, uint32_t addr) {
    asm volatile("ldmatrix.sync.aligned.m8n8.x4.trans.shared.b16 {%0,%1,%2,%3}, [%4];"
                 : "=r"(r[0]), "=r"(r[1]), "=r"(r[2]), "=r"(r[3]) : "r"(addr));
}
__device__ __forceinline__ void ldmatrix_x2t(uint32_t* r, uint32_t addr) {
    asm volatile("ldmatrix.sync.aligned.m8n8.x2.trans.shared.b16 {%0,%1}, [%2];"
                 : "=r"(r[0]), "=r"(r[1]) : "r"(addr));
}
__device__ __forceinline__ void mma16816(float* d, const uint32_t* a, const uint32_t* b) {
    asm volatile(
        "mma.sync.aligned.m16n8k16.row.col.f32.f16.f16.f32 "
        "{%0,%1,%2,%3},{%4,%5,%6,%7},{%8,%9},{%0,%1,%2,%3};"
        : "+f"(d[0]), "+f"(d[1]), "+f"(d[2]), "+f"(d[3])
        : "r"(a[0]), "r"(a[1]), "r"(a[2]), "r"(a[3]), "r"(b[0]), "r"(b[1]));
}
// acquire load (volatile asm — cannot be hoisted or deleted)
__device__ __forceinline__ int ld_acquire_gpu(const int* p) {
    int v;
    asm volatile("ld.acquire.gpu.global.s32 %0, [%1];" : "=r"(v) : "l"(p) : "memory");
    return v;
}
// release reduction
__device__ __forceinline__ void red_release_add(int* p, int v) {
    asm volatile("red.release.gpu.global.add.s32 [%0], %1;" :: "l"(p), "r"(v) : "memory");
}

__device__ __forceinline__ float sigmoidf_(float x) { return 1.f / (1.f + expf(-x)); }

// ---------------------------------------------------------------------------
__global__ void f32_to_f16(const float* __restrict__ in, __half* __restrict__ out, int n)
{
    int i4 = (blockIdx.x * 256 + threadIdx.x) * 4;
    if (i4 < n) {
        float4 v = *reinterpret_cast<const float4*>(in + i4);
        *reinterpret_cast<__half2*>(out + i4)     = __floats2half2_rn(v.x, v.y);
        *reinterpret_cast<__half2*>(out + i4 + 2) = __floats2half2_rn(v.z, v.w);
    }
}

__global__ void init_h16(const float* __restrict__ h0, __half* __restrict__ h16)
{
    int i = blockIdx.x * 256 + threadIdx.x;
    if (i < BH) h16[i] = __float2half_rn(h0[i]);   // seed buffer 0
}

__global__ void reset_cnt(int* cnt)
{
    int i = blockIdx.x * 256 + threadIdx.x;
    if (i < T_ * 2) cnt[i] = 0;
}

// ---------------------------------------------------------------------------
// HGEMM: C_fp32(M,N) = A_fp16(M,K) @ B_fp16(K,N) + bias(N)
// 128x128x32 tile, 256 threads, THREE-stage cp.async pipeline.
// ---------------------------------------------------------------------------
__global__ void __launch_bounds__(256) hgemm(
    const __half* __restrict__ A, const __half* __restrict__ Bm,
    const float* __restrict__ bias, float* __restrict__ C,
    int M, int N, int K)
{
    __shared__ __half As[3][128 * 40];
    __shared__ __half Bs[3][32 * 136];

    const int tid = threadIdx.x;
    const int w = tid >> 5, lane = tid & 31;
    const int bm = blockIdx.y * 128, bn = blockIdx.x * 128;
    const int wm = (w >> 2) * 64, wn = (w & 3) * 32;
    const uint32_t AsU = smem_u32(As), BsU = smem_u32(Bs);

    float acc[4][4][4];
#pragma unroll
    for (int i = 0; i < 4; i++)
#pragma unroll
        for (int j = 0; j < 4; j++)
#pragma unroll
            for (int e = 0; e < 4; e++) acc[i][j][e] = 0.f;

    const int nk = K / 32;

#define LOAD_TILE(kt, buf)                                                        \
    {                                                                             \
        int k0 = (kt) * 32;                                                       \
        _Pragma("unroll")                                                         \
        for (int e = 0; e < 2; e++) {                                             \
            int idx = tid + e * 256;                                              \
            int r = idx >> 2, ch = idx & 3;                                       \
            cp_async16(AsU + ((buf) * 5120 + r * 40 + ch * 8) * 2,                \
                       A + (size_t)(bm + r) * K + k0 + ch * 8);                   \
        }                                                                         \
        _Pragma("unroll")                                                         \
        for (int e = 0; e < 2; e++) {                                             \
            int idx = tid + e * 256;                                              \
            int r = idx >> 4, ch = idx & 15;                                      \
            cp_async16(BsU + ((buf) * 4352 + r * 136 + ch * 8) * 2,               \
                       Bm + (size_t)(k0 + r) * N + bn + ch * 8);                  \
        }                                                                         \
        cp_commit();                                                              \
    }

    LOAD_TILE(0, 0)
    if (nk > 1) LOAD_TILE(1, 1)

    for (int kt = 0; kt < nk; kt++) {
        int buf = kt % 3;
        // buf(kt) ready when ≤1 younger group still pending
        if (kt + 1 < nk) cp_wait_n<1>(); else cp_wait_n<0>();
        __syncthreads();                      // also: all done computing kt-1
        if (kt + 2 < nk) LOAD_TILE(kt + 2, (kt + 2) % 3)  // overwrites buf(kt-1): safe

#pragma unroll
        for (int ks = 0; ks < 2; ks++) {
            uint32_t bfr[4][2];
#pragma unroll
            for (int nf = 0; nf < 4; nf++)
                ldmatrix_x2t(bfr[nf],
                    BsU + (buf * 4352 + (ks * 16 + (lane & 15)) * 136 + wn + nf * 8) * 2);
#pragma unroll
            for (int mf = 0; mf < 4; mf++) {
                uint32_t afr[4];
                ldmatrix_x4(afr,
                    AsU + (buf * 5120 + (wm + mf * 16 + (lane & 15)) * 40
                           + ks * 16 + ((lane >> 4) * 8)) * 2);
#pragma unroll
                for (int nf = 0; nf < 4; nf++) mma16816(acc[mf][nf], afr, bfr[nf]);
            }
        }
        __syncthreads();
    }
#undef LOAD_TILE

    const int g = lane >> 2, t4 = lane & 3;
#pragma unroll
    for (int mf = 0; mf < 4; mf++)
#pragma unroll
        for (int nf = 0; nf < 4; nf++) {
            int row0 = bm + wm + mf * 16 + g;
            int col = bn + wn + nf * 8 + t4 * 2;
            float b0 = bias ? bias[col] : 0.f;
            float b1 = bias ? bias[col + 1] : 0.f;
            C[(size_t)row0 * N + col]           = acc[mf][nf][0] + b0;
            C[(size_t)row0 * N + col + 1]       = acc[mf][nf][1] + b1;
            C[(size_t)(row0 + 8) * N + col]     = acc[mf][nf][2] + b0;
            C[(size_t)(row0 + 8) * N + col + 1] = acc[mf][nf][3] + b1;
        }
}

// ---------------------------------------------------------------------------
// Persistent tensor-core LSTM v5 (= v3b structure + single-poller wait,
// no per-thread fence). 128 CTAs = 64 j-groups x 2 batch halves.
//  - h double-buffered: read buf t&1, write buf (t+1)&1.
//  - one counter per (t,bh); ONLY WARP 0 acquire-polls, then bar.sync
//    broadcasts readiness to the CTA (cuts hot-line L2 traffic 8x).
//  - producer arrival: bar.sync (orders all threads' h-stores) then tid0
//    red.release — release chain through the barrier, no per-thread fence.
//  - WAR-safe: observing cnt[t-1]==64 implies all same-bh CTAs completed
//    their step-(t-1) staging reads of the buffer overwritten at step t.
// ---------------------------------------------------------------------------
constexpr int U_BYTES   = 1024 * 72 * 2;   // 147456
constexpr int A_BYTES   = 32 * 1032 * 2;   // 66048
constexpr int LSTM_SMEM = U_BYTES + A_BYTES;  // 213504

__global__ void __launch_bounds__(256) lstm_layer_tc5(
    const __half* __restrict__ U16,   // (1024, 4096) fp16
    const float* __restrict__ xw,     // (B*T, 4096) fp32, rows b*T+t
    const float* __restrict__ cseed,  // (B,1024) fp32 initial cell
    float* __restrict__ cout,         // (B,1024) fp32 final cell
    __half* __restrict__ h16,         // [2][B][1024] fp16 (buf0 pre-seeded)
    __half* __restrict__ ys16,        // (B*T, 1024) fp16 out
    int* __restrict__ cnt)            // [T][2] arrival counters (zeroed)
{
    extern __shared__ char sm[];
    __half* U_s = (__half*)sm;                 // [1024][72]
    __half* A_s = (__half*)(sm + U_BYTES);     // [32][1032]
    float*  red = (float*)(sm + U_BYTES);      // alias: per-warp [32][10] fp32
    const uint32_t U_u = smem_u32(U_s);
    const uint32_t A_u = smem_u32(A_s);

    const int tid = threadIdx.x;
    const int w = tid >> 5, lane = tid & 31;
    const int jg = blockIdx.x >> 1;            // 0..63
    const int bh = blockIdx.x & 1;             // batch half
    const int j0 = jg * 16;

    // ---- preload U slice: U_s[k][w*8 + 2*gate + jj] = U16[k][gate*H + j0 + 2w + jj]
    for (int i = 0; i < 128; i++) {
        int idx = tid + i * 256;
        int k = idx >> 5;
        int gate = (idx >> 3) & 3;
        int ww = idx & 7;
        *reinterpret_cast<__half2*>(U_s + k * 72 + ww * 8 + 2 * gate) =
            *reinterpret_cast<const __half2*>(U16 + (size_t)k * G4 + gate * H_ + j0 + 2 * ww);
    }
    __syncthreads();

    const int bloc = bh * 32 + lane;
    float2 creg = *reinterpret_cast<const float2*>(cseed + (size_t)bloc * H_ + j0 + 2 * w);

    float* redw = red + w * 320;               // [32][10]

    for (int t = 0; t < T_; t++) {
        // prefetch xw for this lane's two cells (independent of h)
        float2 xg[4];
        {
            size_t xbase = ((size_t)bloc * T_ + t) * (size_t)G4 + j0 + 2 * w;
#pragma unroll
            for (int gg = 0; gg < 4; gg++)
                xg[gg] = __ldg(reinterpret_cast<const float2*>(xw + xbase + (size_t)gg * H_));
        }

        // wait for h[t-1] producers: only warp 0 polls, bar broadcasts
        if (t > 0) {
            if (w == 0) {
                const int* cp = &cnt[(t - 1) * 2 + bh];
                while ((unsigned)ld_acquire_gpu(cp) < 64u) { }
            }
            __syncthreads();
        }

        const __half* hg = h16 + (size_t)(t & 1) * BH + (size_t)bh * 32 * H_;

        // issue all 4 h-staging chunks (256 cols each)
#pragma unroll
        for (int cch = 0; cch < 4; cch++) {
#pragma unroll
            for (int e = 0; e < 4; e++) {
                int idx = tid + e * 256;
                int r = idx >> 5, ch = idx & 31;
                cp_async16(A_u + (r * 1032 + cch * 256 + ch * 8) * 2,
                           hg + (size_t)r * H_ + cch * 256 + ch * 8);
            }
            cp_commit();
        }

        float acc0[4], acc1[4];
#pragma unroll
        for (int e = 0; e < 4; e++) { acc0[e] = 0.f; acc1[e] = 0.f; }

#define LSTM_MMA_CHUNK(C, WAITN)                                                   \
        {                                                                          \
            cp_wait_n<WAITN>();                                                    \
            __syncthreads();                                                       \
            _Pragma("unroll")                                                      \
            for (int ks2 = 0; ks2 < 8; ks2++) {                                    \
                int kk = (C) * 256 + ks2 * 32;                                     \
                uint32_t bq[4];                                                    \
                ldmatrix_x4t(bq, U_u + ((kk + lane) * 72 + w * 8) * 2);            \
                uint32_t a0[4], a1[4];                                             \
                ldmatrix_x4(a0, A_u + (((lane & 15)) * 1032                        \
                                       + kk + (lane >> 4) * 8) * 2);               \
                ldmatrix_x4(a1, A_u + ((16 + (lane & 15)) * 1032                   \
                                       + kk + (lane >> 4) * 8) * 2);               \
                mma16816(acc0, a0, bq);                                            \
                mma16816(acc1, a1, bq);                                            \
                uint32_t a2[4], a3[4];                                             \
                ldmatrix_x4(a2, A_u + (((lane & 15)) * 1032                        \
                                       + kk + 16 + (lane >> 4) * 8) * 2);          \
                ldmatrix_x4(a3, A_u + ((16 + (lane & 15)) * 1032                   \
                                       + kk + 16 + (lane >> 4) * 8) * 2);          \
                mma16816(acc0, a2, bq + 2);                                        \
                mma16816(acc1, a3, bq + 2);                                        \
            }                                                                      \
        }
        LSTM_MMA_CHUNK(0, 3)
        LSTM_MMA_CHUNK(1, 2)
        LSTM_MMA_CHUNK(2, 1)
        LSTM_MMA_CHUNK(3, 0)
#undef LSTM_MMA_CHUNK

        __syncthreads();   // all warps done reading A_s; red alias now safe

        // warp-private gate transpose: redw[row][col], col = 2*gate + jj
        {
            const int g_ = lane >> 2, t4 = lane & 3;
            redw[(g_)      * 10 + 2 * t4]     = acc0[0];
            redw[(g_)      * 10 + 2 * t4 + 1] = acc0[1];
            redw[(g_ + 8)  * 10 + 2 * t4]     = acc0[2];
            redw[(g_ + 8)  * 10 + 2 * t4 + 1] = acc0[3];
            redw[(g_ + 16) * 10 + 2 * t4]     = acc1[0];
            redw[(g_ + 16) * 10 + 2 * t4 + 1] = acc1[1];
            redw[(g_ + 24) * 10 + 2 * t4]     = acc1[2];
            redw[(g_ + 24) * 10 + 2 * t4 + 1] = acc1[3];
        }
        __syncwarp();

        // cell update: lane handles row=lane (bloc), both j
        {
            float iva = redw[lane * 10 + 0] + xg[0].x;
            float ivb = redw[lane * 10 + 1] + xg[0].y;
            float fva = redw[lane * 10 + 2] + xg[1].x;
            float fvb = redw[lane * 10 + 3] + xg[1].y;
            float gva = redw[lane * 10 + 4] + xg[2].x;
            float gvb = redw[lane * 10 + 5] + xg[2].y;
            float ova = redw[lane * 10 + 6] + xg[3].x;
            float ovb = redw[lane * 10 + 7] + xg[3].y;

            float cna = sigmoidf_(fva) * creg.x + sigmoidf_(iva) * tanhf(gva);
            float cnb = sigmoidf_(fvb) * creg.y + sigmoidf_(ivb) * tanhf(gvb);
            float hna = sigmoidf_(ova) * tanhf(cna);
            float hnb = sigmoidf_(ovb) * tanhf(cnb);
            creg.x = cna; creg.y = cnb;

            __half2 h2 = __floats2half2_rn(hna, hnb);
            *reinterpret_cast<__half2*>(
                h16 + (size_t)((t + 1) & 1) * BH + (size_t)bloc * H_ + j0 + 2 * w) = h2;
            *reinterpret_cast<__half2*>(
                ys16 + ((size_t)bloc * T_ + t) * (size_t)H_ + j0 + 2 * w) = h2;
        }

        // arrive: bar.sync orders all threads' h-stores before tid0's release
        __syncthreads();
        if (tid == 0) red_release_add(&cnt[t * 2 + bh], 1);
    }

    // write back final cell state
    *reinterpret_cast<float2*>(cout + (size_t)bloc * H_ + j0 + 2 * w) = creg;
}

// ---------------------------------------------------------------------------
// fc2 split-K: z2(64,36) += z1(64,131072) @ W(131072,36); z2 pre-seeded w/ bias
// ---------------------------------------------------------------------------
constexpr int FC2_SMEM = 256 * 65 * 4 + 256 * 37 * 4;  // 104448

__global__ void __launch_bounds__(256) fc2_split(
    const float* __restrict__ z1, const float* __restrict__ W,
    float* __restrict__ z2)
{
    extern __shared__ float smf[];
    float* As = smf;                 // [256 k][65 m-pad]
    float* Ws = smf + 256 * 65;      // [256 k][37 n-pad]
    const int k0 = blockIdx.x * 256;
    const int tid = threadIdx.x;

    for (int i = 0; i < 16; i++) {
        int idx = tid + i * 256;
        int m = idx >> 6, kc = (idx & 63) * 4;
        float4 v = *reinterpret_cast<const float4*>(z1 + (size_t)m * 131072 + k0 + kc);
        As[(kc + 0) * 65 + m] = v.x;
        As[(kc + 1) * 65 + m] = v.y;
        As[(kc + 2) * 65 + m] = v.z;
        As[(kc + 3) * 65 + m] = v.w;
    }
    for (int i = 0; i < 36; i++) {
        int idx = tid + i * 256;
        int k = idx / 36, n = idx - k * 36;
        Ws[k * 37 + n] = W[(size_t)(k0 + k) * 36 + n];
    }
    __syncthreads();

    const int m = tid & 63, ng = tid >> 6;
    const int n0 = ng * 9;
    float acc[9];
#pragma unroll
    for (int j = 0; j < 9; j++) acc[j] = 0.f;

    for (int k = 0; k < 256; k++) {
        float a = As[k * 65 + m];
#pragma unroll
        for (int j = 0; j < 9; j++) acc[j] = fmaf(a, Ws[k * 37 + n0 + j], acc[j]);
    }
#pragma unroll
    for (int j = 0; j < 9; j++) atomicAdd(&z2[m * 36 + n0 + j], acc[j]);
}

__global__ void z2_init(const float* __restrict__ bias, float* __restrict__ z2)
{
    int i = blockIdx.x * 256 + threadIdx.x;
    if (i < B_ * 36) z2[i] = bias[i % 36];
}

// fc3 (36->6) + fc4 (6->6) + relu
__global__ void fc34_kernel(const float* __restrict__ z2,
                            const float* __restrict__ w3, const float* __restrict__ b3,
                            const float* __restrict__ w4, const float* __restrict__ b4,
                            float* __restrict__ out)
{
    int m = threadIdx.x;
    if (m >= B_) return;
    float t3[6];
#pragma unroll
    for (int n = 0; n < 6; n++) {
        float s = b3[n];
        for (int k = 0; k < 36; k++) s = fmaf(z2[m * 36 + k], w3[k * 6 + n], s);
        t3[n] = s;
    }
#pragma unroll
    for (int n = 0; n < 6; n++) {
        float s = b4[n];
#pragma unroll
        for (int k = 0; k < 6; k++) s = fmaf(t3[k], w4[k * 6 + n], s);
        out[m * 6 + n] = fmaxf(s, 0.f);
    }
}

// ---------------------------------------------------------------------------
extern "C" void kernel_launch(void* const* d_in, const int* in_sizes, int n_in,
                              void* d_out, int out_size)
{
    const float* x     = (const float*)d_in[0];
    const float* h0    = (const float*)d_in[1];
    const float* c0    = (const float*)d_in[2];
    const float* W1    = (const float*)d_in[3];
    const float* U1    = (const float*)d_in[4];
    const float* b1    = (const float*)d_in[5];
    const float* W2    = (const float*)d_in[6];
    const float* U2    = (const float*)d_in[7];
    const float* b2    = (const float*)d_in[8];
    const float* fc1_w = (const float*)d_in[9];
    const float* fc1_b = (const float*)d_in[10];
    const float* fc2_w = (const float*)d_in[11];
    const float* fc2_b = (const float*)d_in[12];
    const float* fc3_w = (const float*)d_in[13];
    const float* fc3_b = (const float*)d_in[14];
    const float* fc4_w = (const float*)d_in[15];
    const float* fc4_b = (const float*)d_in[16];
    float* out = (float*)d_out;

    float *xw, *c, *z1, *z2;
    int* cnt;
    __half *h16, *x16, *W1_16, *U1_16, *W2_16, *U2_16, *fc1w16, *ys1_16, *ys2_16;
    cudaGetSymbolAddress((void**)&xw, g_xw);
    cudaGetSymbolAddress((void**)&c, g_c);
    cudaGetSymbolAddress((void**)&h16, g_h16);
    cudaGetSymbolAddress((void**)&x16, g_x16);
    cudaGetSymbolAddress((void**)&W1_16, g_W1_16);
    cudaGetSymbolAddress((void**)&U1_16, g_U1_16);
    cudaGetSymbolAddress((void**)&W2_16, g_W2_16);
    cudaGetSymbolAddress((void**)&U2_16, g_U2_16);
    cudaGetSymbolAddress((void**)&fc1w16, g_fc1w16);
    cudaGetSymbolAddress((void**)&ys1_16, g_ys1_16);
    cudaGetSymbolAddress((void**)&ys2_16, g_ys2_16);
    cudaGetSymbolAddress((void**)&z1, g_z1);
    cudaGetSymbolAddress((void**)&z2, g_z2);
    cudaGetSymbolAddress((void**)&cnt, g_cnt);

    static bool attr_done = false;
    if (!attr_done) {
        cudaFuncSetAttribute(lstm_layer_tc5,
                             cudaFuncAttributeMaxDynamicSharedMemorySize, LSTM_SMEM);
        cudaFuncSetAttribute(fc2_split,
                             cudaFuncAttributeMaxDynamicSharedMemorySize, FC2_SMEM);
        attr_done = true;
    }

    const int MT = B_ * T_;  // 16384

    auto conv = [](const float* src, __half* dst, int n) {
        f32_to_f16<<<(n / 4 + 255) / 256, 256>>>(src, dst, n);
    };
    conv(x, x16, MT * D_);
    conv(W1, W1_16, D_ * G4);
    conv(U1, U1_16, H_ * G4);
    conv(W2, W2_16, H_ * G4);
    conv(U2, U2_16, H_ * G4);
    conv(fc1_w, fc1w16, H_ * (H_ / 2));
    init_h16<<<BH / 256, 256>>>(h0, h16);

    // xw = x @ W1 + b1
    hgemm<<<dim3(G4 / 128, MT / 128), 256>>>(x16, W1_16, b1, xw, MT, G4, D_);

    // LSTM layer 1 (c seeded from c0, final c -> g_c)
    reset_cnt<<<2, 256>>>(cnt);
    lstm_layer_tc5<<<128, 256, LSTM_SMEM>>>(U1_16, xw, c0, c, h16, ys1_16, cnt);

    // xw = ys1 @ W2 + b2
    hgemm<<<dim3(G4 / 128, MT / 128), 256>>>(ys1_16, W2_16, b2, xw, MT, G4, H_);

    // LSTM layer 2 (h16 buf0 / c carry over — matches reference seeding)
    reset_cnt<<<2, 256>>>(cnt);
    lstm_layer_tc5<<<128, 256, LSTM_SMEM>>>(U2_16, xw, c, c, h16, ys2_16, cnt);

    // z1 = ys2 @ fc1_w + fc1_b
    hgemm<<<dim3((H_ / 2) / 128, MT / 128), 256>>>(ys2_16, fc1w16, fc1_b, z1,
                                                   MT, H_ / 2, H_);

    // fc2: z2 = bias, then split-K accumulate
    z2_init<<<(B_ * 36 + 255) / 256, 256>>>(fc2_b, z2);
    fc2_split<<<512, 256, FC2_SMEM>>>(z1, fc2_w, z2);

    // fc3 + fc4 + relu -> out (64, 6)
    fc34_kernel<<<1, 64>>>(z2, fc3_w, fc3_b, fc4_w, fc4_b, out);
}

// round 11
// speedup vs baseline: 1.2915x; 1.0423x over previous
#include <cuda_runtime.h>
#include <cuda_fp16.h>
#include <math.h>
#include <stdint.h>

// Problem constants
constexpr int B_ = 64;
constexpr int T_ = 256;
constexpr int D_ = 512;
constexpr int H_ = 1024;
constexpr int G4 = 4 * H_;         // 4096
constexpr int BH = B_ * H_;        // 65536

// ------------------------- device scratch (no allocs) ----------------------
__device__ float  g_xw[(size_t)B_ * T_ * G4];        // (B*T, 4H) fp32
__device__ float  g_c[BH];                           // cell state fp32
__device__ __half g_h16[2 * BH];                     // double-buffered hidden
__device__ __half g_x16[(size_t)B_ * T_ * D_];
__device__ __half g_W1_16[(size_t)D_ * G4];
__device__ __half g_U1_16[(size_t)H_ * G4];
__device__ __half g_W2_16[(size_t)H_ * G4];
__device__ __half g_U2_16[(size_t)H_ * G4];
__device__ __half g_fc1w16[(size_t)H_ * (H_ / 2)];
__device__ __half g_ys1_16[(size_t)B_ * T_ * H_];
__device__ __half g_ys2_16[(size_t)B_ * T_ * H_];
__device__ float  g_z1[(size_t)B_ * T_ * (H_ / 2)];
__device__ float  g_z2[B_ * 36];
__device__ int    g_cnt[2 * T_ * 2];                 // [layer][t][bh] arrivals

// ------------------------------ PTX helpers --------------------------------
__device__ __forceinline__ uint32_t smem_u32(const void* p) {
    uint32_t a;
    asm("{ .reg .u64 t; cvta.to.shared.u64 t, %1; cvt.u32.u64 %0, t; }"
        : "=r"(a) : "l"(p));
    return a;
}
__device__ __forceinline__ void cp_async16(uint32_t dst, const void* src) {
    asm volatile("cp.async.cg.shared.global [%0], [%1], 16;" :: "r"(dst), "l"(src));
}
__device__ __forceinline__ void cp_commit() {
    asm volatile("cp.async.commit_group;");
}
template <int N> __device__ __forceinline__ void cp_wait_n() {
    asm volatile("cp.async.wait_group %0;" :: "n"(N));
}
__device__ __forceinline__ void ldmatrix_x4(uint32_t* r, uint32_t addr) {
    asm volatile("ldmatrix.sync.aligned.m8n8.x4.shared.b16 {%0,%1,%2,%3}, [%4];"
                 : "=r"(r[0]), "=r"(r[1]), "=r"(r[2]), "=r"(r[3]) : "r"(addr));
}
__device__ __forceinline__ void ldmatrix_x4t(uint32_t* r, uint32_t addr) {
    asm volatile("ldmatrix.sync.aligned.m8n8.x4.trans.shared.b16 {%0,%1,%2,%3}, [%4];"
                 : "=r"(r[0]), "=r"(r[1]), "=r"(r[2]), "=r"(r[3]) : "r"(addr));
}
__device__ __forceinline__ void ldmatrix_x2t(uint32_t* r, uint32_t addr) {
    asm volatile("ldmatrix.sync.aligned.m8n8.x2.trans.shared.b16 {%0,%1}, [%2];"
                 : "=r"(r[0]), "=r"(r[1]) : "r"(addr));
}
__device__ __forceinline__ void mma16816(float* d, const uint32_t* a, const uint32_t* b) {
    asm volatile(
        "mma.sync.aligned.m16n8k16.row.col.f32.f16.f16.f32 "
        "{%0,%1,%2,%3},{%4,%5,%6,%7},{%8,%9},{%0,%1,%2,%3};"
        : "+f"(d[0]), "+f"(d[1]), "+f"(d[2]), "+f"(d[3])
        : "r"(a[0]), "r"(a[1]), "r"(a[2]), "r"(a[3]), "r"(b[0]), "r"(b[1]));
}
// acquire load (volatile asm — cannot be hoisted or deleted)
__device__ __forceinline__ int ld_acquire_gpu(const int* p) {
    int v;
    asm volatile("ld.acquire.gpu.global.s32 %0, [%1];" : "=r"(v) : "l"(p) : "memory");
    return v;
}
// release reduction
__device__ __forceinline__ void red_release_add(int* p, int v) {
    asm volatile("red.release.gpu.global.add.s32 [%0], %1;" :: "l"(p), "r"(v) : "memory");
}

// fast gate math: MUFU-based, rel err ~2e-7 (invisible vs fp16 5.6e-4)
__device__ __forceinline__ float fast_sigmoid(float x) {
    return __fdividef(1.f, 1.f + __expf(-x));     // x->-inf: 1/inf=0; x->+inf: 1
}
__device__ __forceinline__ float fast_tanh(float x) {
    return 1.f - __fdividef(2.f, __expf(2.f * x) + 1.f);  // saturates to ±1, no NaN
}

// ---------------------------------------------------------------------------
__global__ void f32_to_f16(const float* __restrict__ in, __half* __restrict__ out, int n)
{
    int i4 = (blockIdx.x * 256 + threadIdx.x) * 4;
    if (i4 < n) {
        float4 v = *reinterpret_cast<const float4*>(in + i4);
        *reinterpret_cast<__half2*>(out + i4)     = __floats2half2_rn(v.x, v.y);
        *reinterpret_cast<__half2*>(out + i4 + 2) = __floats2half2_rn(v.z, v.w);
    }
}

// seed h16 buf0 from h0, zero BOTH layers' arrival counters
__global__ void init_all(const float* __restrict__ h0, __half* __restrict__ h16,
                         int* __restrict__ cnt)
{
    int i = blockIdx.x * 256 + threadIdx.x;
    if (i < BH) h16[i] = __float2half_rn(h0[i]);
    if (i < 2 * T_ * 2) cnt[i] = 0;
}

// ---------------------------------------------------------------------------
// HGEMM: C_fp32(M,N) = A_fp16(M,K) @ B_fp16(K,N) + bias(N)
// 128x128x32 tile, 256 threads, THREE-stage cp.async pipeline.
// ---------------------------------------------------------------------------
__global__ void __launch_bounds__(256) hgemm(
    const __half* __restrict__ A, const __half* __restrict__ Bm,
    const float* __restrict__ bias, float* __restrict__ C,
    int M, int N, int K)
{
    __shared__ __half As[3][128 * 40];
    __shared__ __half Bs[3][32 * 136];

    const int tid = threadIdx.x;
    const int w = tid >> 5, lane = tid & 31;
    const int bm = blockIdx.y * 128, bn = blockIdx.x * 128;
    const int wm = (w >> 2) * 64, wn = (w & 3) * 32;
    const uint32_t AsU = smem_u32(As), BsU = smem_u32(Bs);

    float acc[4][4][4];
#pragma unroll
    for (int i = 0; i < 4; i++)
#pragma unroll
        for (int j = 0; j < 4; j++)
#pragma unroll
            for (int e = 0; e < 4; e++) acc[i][j][e] = 0.f;

    const int nk = K / 32;

#define LOAD_TILE(kt, buf)                                                        \
    {                                                                             \
        int k0 = (kt) * 32;                                                       \
        _Pragma("unroll")                                                         \
        for (int e = 0; e < 2; e++) {                                             \
            int idx = tid + e * 256;                                              \
            int r = idx >> 2, ch = idx & 3;                                       \
            cp_async16(AsU + ((buf) * 5120 + r * 40 + ch * 8) * 2,                \
                       A + (size_t)(bm + r) * K + k0 + ch * 8);                   \
        }                                                                         \
        _Pragma("unroll")                                                         \
        for (int e = 0; e < 2; e++) {                                             \
            int idx = tid + e * 256;                                              \
            int r = idx >> 4, ch = idx & 15;                                      \
            cp_async16(BsU + ((buf) * 4352 + r * 136 + ch * 8) * 2,               \
                       Bm + (size_t)(k0 + r) * N + bn + ch * 8);                  \
        }                                                                         \
        cp_commit();                                                              \
    }

    LOAD_TILE(0, 0)
    if (nk > 1) LOAD_TILE(1, 1)

    for (int kt = 0; kt < nk; kt++) {
        int buf = kt % 3;
        if (kt + 1 < nk) cp_wait_n<1>(); else cp_wait_n<0>();
        __syncthreads();
        if (kt + 2 < nk) LOAD_TILE(kt + 2, (kt + 2) % 3)

#pragma unroll
        for (int ks = 0; ks < 2; ks++) {
            uint32_t bfr[4][2];
#pragma unroll
            for (int nf = 0; nf < 4; nf++)
                ldmatrix_x2t(bfr[nf],
                    BsU + (buf * 4352 + (ks * 16 + (lane & 15)) * 136 + wn + nf * 8) * 2);
#pragma unroll
            for (int mf = 0; mf < 4; mf++) {
                uint32_t afr[4];
                ldmatrix_x4(afr,
                    AsU + (buf * 5120 + (wm + mf * 16 + (lane & 15)) * 40
                           + ks * 16 + ((lane >> 4) * 8)) * 2);
#pragma unroll
                for (int nf = 0; nf < 4; nf++) mma16816(acc[mf][nf], afr, bfr[nf]);
            }
        }
        __syncthreads();
    }
#undef LOAD_TILE

    const int g = lane >> 2, t4 = lane & 3;
#pragma unroll
    for (int mf = 0; mf < 4; mf++)
#pragma unroll
        for (int nf = 0; nf < 4; nf++) {
            int row0 = bm + wm + mf * 16 + g;
            int col = bn + wn + nf * 8 + t4 * 2;
            float b0 = bias ? bias[col] : 0.f;
            float b1 = bias ? bias[col + 1] : 0.f;
            C[(size_t)row0 * N + col]           = acc[mf][nf][0] + b0;
            C[(size_t)row0 * N + col + 1]       = acc[mf][nf][1] + b1;
            C[(size_t)(row0 + 8) * N + col]     = acc[mf][nf][2] + b0;
            C[(size_t)(row0 + 8) * N + col + 1] = acc[mf][nf][3] + b1;
        }
}

// ---------------------------------------------------------------------------
// Persistent tensor-core LSTM v6 (= v5 + fast-math gates).
// 128 CTAs = 64 j-groups x 2 batch halves; M=32, N=64 gate cols, K=1024.
//  - h double-buffered: read buf t&1, write buf (t+1)&1.
//  - one counter per (t,bh); only warp 0 acquire-polls, bar.sync broadcasts.
//  - producer arrival: bar.sync then tid0 red.release (release chain
//    through the barrier).
//  - WAR-safe: observing cnt[t-1]==64 implies all same-bh CTAs completed
//    their step-(t-1) staging reads of the buffer overwritten at step t.
// ---------------------------------------------------------------------------
constexpr int U_BYTES   = 1024 * 72 * 2;   // 147456
constexpr int A_BYTES   = 32 * 1032 * 2;   // 66048
constexpr int LSTM_SMEM = U_BYTES + A_BYTES;  // 213504

__global__ void __launch_bounds__(256) lstm_layer_tc6(
    const __half* __restrict__ U16,   // (1024, 4096) fp16
    const float* __restrict__ xw,     // (B*T, 4096) fp32, rows b*T+t
    const float* __restrict__ cseed,  // (B,1024) fp32 initial cell
    float* __restrict__ cout,         // (B,1024) fp32 final cell
    __half* __restrict__ h16,         // [2][B][1024] fp16 (buf0 pre-seeded)
    __half* __restrict__ ys16,        // (B*T, 1024) fp16 out
    int* __restrict__ cnt)            // [T][2] arrival counters (zeroed)
{
    extern __shared__ char sm[];
    __half* U_s = (__half*)sm;                 // [1024][72]
    __half* A_s = (__half*)(sm + U_BYTES);     // [32][1032]
    float*  red = (float*)(sm + U_BYTES);      // alias: per-warp [32][10] fp32
    const uint32_t U_u = smem_u32(U_s);
    const uint32_t A_u = smem_u32(A_s);

    const int tid = threadIdx.x;
    const int w = tid >> 5, lane = tid & 31;
    const int jg = blockIdx.x >> 1;            // 0..63
    const int bh = blockIdx.x & 1;             // batch half
    const int j0 = jg * 16;

    // ---- preload U slice: U_s[k][w*8 + 2*gate + jj] = U16[k][gate*H + j0 + 2w + jj]
    for (int i = 0; i < 128; i++) {
        int idx = tid + i * 256;
        int k = idx >> 5;
        int gate = (idx >> 3) & 3;
        int ww = idx & 7;
        *reinterpret_cast<__half2*>(U_s + k * 72 + ww * 8 + 2 * gate) =
            *reinterpret_cast<const __half2*>(U16 + (size_t)k * G4 + gate * H_ + j0 + 2 * ww);
    }
    __syncthreads();

    const int bloc = bh * 32 + lane;
    float2 creg = *reinterpret_cast<const float2*>(cseed + (size_t)bloc * H_ + j0 + 2 * w);

    float* redw = red + w * 320;               // [32][10]

    for (int t = 0; t < T_; t++) {
        // prefetch xw for this lane's two cells (independent of h)
        float2 xg[4];
        {
            size_t xbase = ((size_t)bloc * T_ + t) * (size_t)G4 + j0 + 2 * w;
#pragma unroll
            for (int gg = 0; gg < 4; gg++)
                xg[gg] = __ldg(reinterpret_cast<const float2*>(xw + xbase + (size_t)gg * H_));
        }

        // wait for h[t-1] producers: only warp 0 polls, bar broadcasts
        if (t > 0) {
            if (w == 0) {
                const int* cp = &cnt[(t - 1) * 2 + bh];
                while ((unsigned)ld_acquire_gpu(cp) < 64u) { }
            }
            __syncthreads();
        }

        const __half* hg = h16 + (size_t)(t & 1) * BH + (size_t)bh * 32 * H_;

        // issue all 4 h-staging chunks (256 cols each)
#pragma unroll
        for (int cch = 0; cch < 4; cch++) {
#pragma unroll
            for (int e = 0; e < 4; e++) {
                int idx = tid + e * 256;
                int r = idx >> 5, ch = idx & 31;
                cp_async16(A_u + (r * 1032 + cch * 256 + ch * 8) * 2,
                           hg + (size_t)r * H_ + cch * 256 + ch * 8);
            }
            cp_commit();
        }

        float acc0[4], acc1[4];
#pragma unroll
        for (int e = 0; e < 4; e++) { acc0[e] = 0.f; acc1[e] = 0.f; }

#define LSTM_MMA_CHUNK(C, WAITN)                                                   \
        {                                                                          \
            cp_wait_n<WAITN>();                                                    \
            __syncthreads();                                                       \
            _Pragma("unroll")                                                      \
            for (int ks2 = 0; ks2 < 8; ks2++) {                                    \
                int kk = (C) * 256 + ks2 * 32;                                     \
                uint32_t bq[4];                                                    \
                ldmatrix_x4t(bq, U_u + ((kk + lane) * 72 + w * 8) * 2);            \
                uint32_t a0[4], a1[4];                                             \
                ldmatrix_x4(a0, A_u + (((lane & 15)) * 1032                        \
                                       + kk + (lane >> 4) * 8) * 2);               \
                ldmatrix_x4(a1, A_u + ((16 + (lane & 15)) * 1032                   \
                                       + kk + (lane >> 4) * 8) * 2);               \
                mma16816(acc0, a0, bq);                                            \
                mma16816(acc1, a1, bq);                                            \
                uint32_t a2[4], a3[4];                                             \
                ldmatrix_x4(a2, A_u + (((lane & 15)) * 1032                        \
                                       + kk + 16 + (lane >> 4) * 8) * 2);          \
                ldmatrix_x4(a3, A_u + ((16 + (lane & 15)) * 1032                   \
                                       + kk + 16 + (lane >> 4) * 8) * 2);          \
                mma16816(acc0, a2, bq + 2);                                        \
                mma16816(acc1, a3, bq + 2);                                        \
            }                                                                      \
        }
        LSTM_MMA_CHUNK(0, 3)
        LSTM_MMA_CHUNK(1, 2)
        LSTM_MMA_CHUNK(2, 1)
        LSTM_MMA_CHUNK(3, 0)
#undef LSTM_MMA_CHUNK

        __syncthreads();   // all warps done reading A_s; red alias now safe

        // warp-private gate transpose: redw[row][col], col = 2*gate + jj
        {
            const int g_ = lane >> 2, t4 = lane & 3;
            redw[(g_)      * 10 + 2 * t4]     = acc0[0];
            redw[(g_)      * 10 + 2 * t4 + 1] = acc0[1];
            redw[(g_ + 8)  * 10 + 2 * t4]     = acc0[2];
            redw[(g_ + 8)  * 10 + 2 * t4 + 1] = acc0[3];
            redw[(g_ + 16) * 10 + 2 * t4]     = acc1[0];
            redw[(g_ + 16) * 10 + 2 * t4 + 1] = acc1[1];
            redw[(g_ + 24) * 10 + 2 * t4]     = acc1[2];
            redw[(g_ + 24) * 10 + 2 * t4 + 1] = acc1[3];
        }
        __syncwarp();

        // cell update: lane handles row=lane (bloc), both j — fast-math gates
        {
            float iva = redw[lane * 10 + 0] + xg[0].x;
            float ivb = redw[lane * 10 + 1] + xg[0].y;
            float fva = redw[lane * 10 + 2] + xg[1].x;
            float fvb = redw[lane * 10 + 3] + xg[1].y;
            float gva = redw[lane * 10 + 4] + xg[2].x;
            float gvb = redw[lane * 10 + 5] + xg[2].y;
            float ova = redw[lane * 10 + 6] + xg[3].x;
            float ovb = redw[lane * 10 + 7] + xg[3].y;

            float cna = fast_sigmoid(fva) * creg.x + fast_sigmoid(iva) * fast_tanh(gva);
            float cnb = fast_sigmoid(fvb) * creg.y + fast_sigmoid(ivb) * fast_tanh(gvb);
            float hna = fast_sigmoid(ova) * fast_tanh(cna);
            float hnb = fast_sigmoid(ovb) * fast_tanh(cnb);
            creg.x = cna; creg.y = cnb;

            __half2 h2 = __floats2half2_rn(hna, hnb);
            *reinterpret_cast<__half2*>(
                h16 + (size_t)((t + 1) & 1) * BH + (size_t)bloc * H_ + j0 + 2 * w) = h2;
            *reinterpret_cast<__half2*>(
                ys16 + ((size_t)bloc * T_ + t) * (size_t)H_ + j0 + 2 * w) = h2;
        }

        // arrive: bar.sync orders all threads' h-stores before tid0's release
        __syncthreads();
        if (tid == 0) red_release_add(&cnt[t * 2 + bh], 1);
    }

    // write back final cell state
    *reinterpret_cast<float2*>(cout + (size_t)bloc * H_ + j0 + 2 * w) = creg;
}

// ---------------------------------------------------------------------------
// fc2 split-K: z2(64,36) += z1(64,131072) @ W(131072,36); z2 pre-seeded w/ bias
// ---------------------------------------------------------------------------
constexpr int FC2_SMEM = 256 * 65 * 4 + 256 * 37 * 4;  // 104448

__global__ void __launch_bounds__(256) fc2_split(
    const float* __restrict__ z1, const float* __restrict__ W,
    float* __restrict__ z2)
{
    extern __shared__ float smf[];
    float* As = smf;                 // [256 k][65 m-pad]
    float* Ws = smf + 256 * 65;      // [256 k][37 n-pad]
    const int k0 = blockIdx.x * 256;
    const int tid = threadIdx.x;

    for (int i = 0; i < 16; i++) {
        int idx = tid + i * 256;
        int m = idx >> 6, kc = (idx & 63) * 4;
        float4 v = *reinterpret_cast<const float4*>(z1 + (size_t)m * 131072 + k0 + kc);
        As[(kc + 0) * 65 + m] = v.x;
        As[(kc + 1) * 65 + m] = v.y;
        As[(kc + 2) * 65 + m] = v.z;
        As[(kc + 3) * 65 + m] = v.w;
    }
    for (int i = 0; i < 36; i++) {
        int idx = tid + i * 256;
        int k = idx / 36, n = idx - k * 36;
        Ws[k * 37 + n] = W[(size_t)(k0 + k) * 36 + n];
    }
    __syncthreads();

    const int m = tid & 63, ng = tid >> 6;
    const int n0 = ng * 9;
    float acc[9];
#pragma unroll
    for (int j = 0; j < 9; j++) acc[j] = 0.f;

    for (int k = 0; k < 256; k++) {
        float a = As[k * 65 + m];
#pragma unroll
        for (int j = 0; j < 9; j++) acc[j] = fmaf(a, Ws[k * 37 + n0 + j], acc[j]);
    }
#pragma unroll
    for (int j = 0; j < 9; j++) atomicAdd(&z2[m * 36 + n0 + j], acc[j]);
}

__global__ void z2_init(const float* __restrict__ bias, float* __restrict__ z2)
{
    int i = blockIdx.x * 256 + threadIdx.x;
    if (i < B_ * 36) z2[i] = bias[i % 36];
}

// fc3 (36->6) + fc4 (6->6) + relu
__global__ void fc34_kernel(const float* __restrict__ z2,
                            const float* __restrict__ w3, const float* __restrict__ b3,
                            const float* __restrict__ w4, const float* __restrict__ b4,
                            float* __restrict__ out)
{
    int m = threadIdx.x;
    if (m >= B_) return;
    float t3[6];
#pragma unroll
    for (int n = 0; n < 6; n++) {
        float s = b3[n];
        for (int k = 0; k < 36; k++) s = fmaf(z2[m * 36 + k], w3[k * 6 + n], s);
        t3[n] = s;
    }
#pragma unroll
    for (int n = 0; n < 6; n++) {
        float s = b4[n];
#pragma unroll
        for (int k = 0; k < 6; k++) s = fmaf(t3[k], w4[k * 6 + n], s);
        out[m * 6 + n] = fmaxf(s, 0.f);
    }
}

// ---------------------------------------------------------------------------
extern "C" void kernel_launch(void* const* d_in, const int* in_sizes, int n_in,
                              void* d_out, int out_size)
{
    const float* x     = (const float*)d_in[0];
    const float* h0    = (const float*)d_in[1];
    const float* c0    = (const float*)d_in[2];
    const float* W1    = (const float*)d_in[3];
    const float* U1    = (const float*)d_in[4];
    const float* b1    = (const float*)d_in[5];
    const float* W2    = (const float*)d_in[6];
    const float* U2    = (const float*)d_in[7];
    const float* b2    = (const float*)d_in[8];
    const float* fc1_w = (const float*)d_in[9];
    const float* fc1_b = (const float*)d_in[10];
    const float* fc2_w = (const float*)d_in[11];
    const float* fc2_b = (const float*)d_in[12];
    const float* fc3_w = (const float*)d_in[13];
    const float* fc3_b = (const float*)d_in[14];
    const float* fc4_w = (const float*)d_in[15];
    const float* fc4_b = (const float*)d_in[16];
    float* out = (float*)d_out;

    float *xw, *c, *z1, *z2;
    int* cnt;
    __half *h16, *x16, *W1_16, *U1_16, *W2_16, *U2_16, *fc1w16, *ys1_16, *ys2_16;
    cudaGetSymbolAddress((void**)&xw, g_xw);
    cudaGetSymbolAddress((void**)&c, g_c);
    cudaGetSymbolAddress((void**)&h16, g_h16);
    cudaGetSymbolAddress((void**)&x16, g_x16);
    cudaGetSymbolAddress((void**)&W1_16, g_W1_16);
    cudaGetSymbolAddress((void**)&U1_16, g_U1_16);
    cudaGetSymbolAddress((void**)&W2_16, g_W2_16);
    cudaGetSymbolAddress((void**)&U2_16, g_U2_16);
    cudaGetSymbolAddress((void**)&fc1w16, g_fc1w16);
    cudaGetSymbolAddress((void**)&ys1_16, g_ys1_16);
    cudaGetSymbolAddress((void**)&ys2_16, g_ys2_16);
    cudaGetSymbolAddress((void**)&z1, g_z1);
    cudaGetSymbolAddress((void**)&z2, g_z2);
    cudaGetSymbolAddress((void**)&cnt, g_cnt);

    static bool attr_done = false;
    if (!attr_done) {
        cudaFuncSetAttribute(lstm_layer_tc6,
                             cudaFuncAttributeMaxDynamicSharedMemorySize, LSTM_SMEM);
        cudaFuncSetAttribute(fc2_split,
                             cudaFuncAttributeMaxDynamicSharedMemorySize, FC2_SMEM);
        attr_done = true;
    }

    const int MT = B_ * T_;  // 16384

    auto conv = [](const float* src, __half* dst, int n) {
        f32_to_f16<<<(n / 4 + 255) / 256, 256>>>(src, dst, n);
    };

    // Launch order chosen so ncu (-s 5 -c 1) profiles lstm_layer_tc6:
    //   0: conv x   1: conv W1   2: hgemm1   3: conv U1   4: init_all   5: LSTM1
    conv(x, x16, MT * D_);                                           // 0
    conv(W1, W1_16, D_ * G4);                                        // 1
    hgemm<<<dim3(G4 / 128, MT / 128), 256>>>(x16, W1_16, b1, xw,     // 2
                                             MT, G4, D_);
    conv(U1, U1_16, H_ * G4);                                        // 3
    init_all<<<BH / 256, 256>>>(h0, h16, cnt);                       // 4
    lstm_layer_tc6<<<128, 256, LSTM_SMEM>>>(U1_16, xw, c0, c,        // 5
                                            h16, ys1_16, cnt);

    // remaining conversions (independent of LSTM1; needed before consumers)
    conv(W2, W2_16, H_ * G4);
    conv(U2, U2_16, H_ * G4);
    conv(fc1_w, fc1w16, H_ * (H_ / 2));

    // xw = ys1 @ W2 + b2
    hgemm<<<dim3(G4 / 128, MT / 128), 256>>>(ys1_16, W2_16, b2, xw, MT, G4, H_);

    // LSTM layer 2 (h16 buf0 / c carry over — matches reference seeding)
    lstm_layer_tc6<<<128, 256, LSTM_SMEM>>>(U2_16, xw, c, c, h16, ys2_16,
                                            cnt + T_ * 2);

    // z1 = ys2 @ fc1_w + fc1_b
    hgemm<<<dim3((H_ / 2) / 128, MT / 128), 256>>>(ys2_16, fc1w16, fc1_b, z1,
                                                   MT, H_ / 2, H_);

    // fc2: z2 = bias, then split-K accumulate
    z2_init<<<(B_ * 36 + 255) / 256, 256>>>(fc2_b, z2);
    fc2_split<<<512, 256, FC2_SMEM>>>(z1, fc2_w, z2);

    // fc3 + fc4 + relu -> out (64, 6)
    fc34_kernel<<<1, 64>>>(z2, fc3_w, fc3_b, fc4_w, fc4_b, out);
}